// round 8
// baseline (speedup 1.0000x reference)
#include <cuda_runtime.h>
#include <cstdint>
#include <cstddef>

// Problem dims
#define B   512
#define T   512
#define IN  128
#define H   256
#define H3  768
#define OUT 128
#define BT  (B * T)

// Step tiling
#define NCT    8      // column tiles over H (256/32)
#define CTILE  32     // h-cols per tile
#define GC     96     // gate cols per tile (3 * CTILE)
#define NBLK   128    // persistent grid size (8 col-tiles x 16 row-blocks)

// persistent kernel smem: whole W slab + unpadded h tile = exactly 128 KiB
#define WALL_BYTES  (H * GC * 4)                // 98304
#define HS_BYTES    (32 * H * 4)                // 32768
#define SMEM_PERS   (WALL_BYTES + HS_BYTES)     // 131072

// ig_gemm dynamic smem: X 64x128 + W 128x64
#define IG_XS_BYTES (64 * IN * 4)               // 32768
#define IG_WS_BYTES (IN * 64 * 4)               // 32768
#define SMEM_IG     (IG_XS_BYTES + IG_WS_BYTES) // 65536

// ---------------------------------------------------------------------------
// Static device scratch (module-load allocation, permitted)
// ---------------------------------------------------------------------------
__device__ float g_IG[(size_t)BT * H3];                 // input gates [t][b][j]
__device__ float g_WihT[IN * H3];                       // W_ih^T [k][j]
__device__ __align__(16) float g_Wpack[NCT * H * GC];   // W_hh packed [ct][k][gc]
__device__ float g_WLt[H * OUT];                        // w_lin^T [k][o]
__device__ __align__(16) float g_h[2][B * H];           // ping-pong hidden state

// grid-barrier state (two-phase, self-resetting)
__device__ unsigned g_bar_count = 0;
__device__ volatile unsigned g_bar_gen = 0;

// ---------------------------------------------------------------------------
// helpers
// ---------------------------------------------------------------------------
__device__ __forceinline__ void fma2(unsigned long long &acc,
                                     unsigned long long a,
                                     unsigned long long b) {
    asm("fma.rn.f32x2 %0, %1, %2, %0;" : "+l"(acc) : "l"(a), "l"(b));
}
__device__ __forceinline__ unsigned long long dup2(float x) {
    unsigned long long r;
    asm("mov.b64 %0, {%1, %1};" : "=l"(r) : "f"(x));
    return r;
}
__device__ __forceinline__ float2 unpack2(unsigned long long v) {
    float2 f;
    asm("mov.b64 {%0, %1}, %2;" : "=f"(f.x), "=f"(f.y) : "l"(v));
    return f;
}
// cp.async.cg: 16B global->shared, L2-only (no L1) — gives coherent h reads
// inside the persistent kernel.
__device__ __forceinline__ void cp16(uint32_t s, const void* g) {
    asm volatile("cp.async.cg.shared.global [%0], [%1], 16;" :: "r"(s), "l"(g));
}
__device__ __forceinline__ void cp_commit() {
    asm volatile("cp.async.commit_group;");
}
__device__ __forceinline__ void cp_wait0() {
    asm volatile("cp.async.wait_group 0;");
}

__device__ __forceinline__ float sigmoidf_(float x) {
    return __fdividef(1.0f, 1.0f + __expf(-x));
}
__device__ __forceinline__ float tanhf_(float x) {
    return __fdividef(2.0f, 1.0f + __expf(-2.0f * x)) - 1.0f;
}

// All-CTA barrier. Safe because grid (128 CTAs, 1/SM) is fully co-resident.
__device__ __forceinline__ void grid_barrier() {
    __syncthreads();                       // all threads done with this step
    if (threadIdx.x == 0) {
        __threadfence();                   // h_out STGs visible at L2
        unsigned gen = g_bar_gen;
        if (atomicAdd(&g_bar_count, 1u) == NBLK - 1u) {
            g_bar_count = 0;               // reset BEFORE release (two-phase)
            __threadfence();
            g_bar_gen = gen + 1u;          // release
        } else {
            while (g_bar_gen == gen) { __nanosleep(64); }
        }
    }
    __syncthreads();                       // broadcast release to all threads
}

// ---------------------------------------------------------------------------
// Prep: transposes + W_hh packing + h0 zero. One-shot, tiny.
// ---------------------------------------------------------------------------
__global__ void prep_kernel(const float* __restrict__ w_ih,
                            const float* __restrict__ w_hh,
                            const float* __restrict__ w_lin) {
    int i = blockIdx.x * blockDim.x + threadIdx.x;
    if (i < IN * H3) {                       // w_ih: (H3, IN) -> [k][j]
        int j = i / IN, k = i % IN;
        g_WihT[k * H3 + j] = w_ih[i];
    }
    if (i < NCT * H * GC) {                  // w_hh: (H3, H) -> [ct][k][g*32+cc]
        int gc = i % GC;
        int k  = (i / GC) % H;
        int ct = i / (GC * H);
        int g  = gc / CTILE, cc = gc % CTILE;
        g_Wpack[i] = w_hh[(g * H + ct * CTILE + cc) * H + k];
    }
    if (i < OUT * H) {                       // w_lin: (OUT, H) -> [k][o]
        int o = i / H, k = i % H;
        g_WLt[k * OUT + o] = w_lin[i];
    }
    if (i < B * H) g_h[0][i] = 0.0f;
    if (i == 0) g_bar_count = 0;             // barrier hygiene
}

// ---------------------------------------------------------------------------
// IG GEMM: g_IG[t][b][j] = x[b][t][:] . w_ih[j][:] + bias_g[j]
// Tile 64 bt-rows x 64 j-cols, K=128. 256 threads, thread = 4 rows x 4 cols.
// ---------------------------------------------------------------------------
__global__ __launch_bounds__(256) void ig_gemm(const float* __restrict__ x,
                                               const float* __restrict__ bias_g) {
    extern __shared__ __align__(16) unsigned char ig_smem[];
    float* Xs = (float*)ig_smem;                     // [row][k] 64x128
    float* Ws = (float*)(ig_smem + IG_XS_BYTES);     // [k][j]   128x64

    int tid = threadIdx.x;
    int bt0 = blockIdx.y * 64;
    int j0  = blockIdx.x * 64;

    {
        const float4* src = (const float4*)(x + (size_t)bt0 * IN);
        float4* dst = (float4*)Xs;
        #pragma unroll
        for (int i = 0; i < 8; i++) dst[tid + i * 256] = src[tid + i * 256];
    }
    {
        #pragma unroll
        for (int i = 0; i < 8; i++) {
            int f = tid + i * 256;
            int k = f >> 4, j4 = (f & 15) << 2;
            *(float4*)&Ws[k * 64 + j4] =
                *(const float4*)&g_WihT[k * H3 + j0 + j4];
        }
    }
    __syncthreads();

    int c = tid & 15;   // 4 cols: 4c..4c+3
    int r = tid >> 4;   // 4 rows: 4r..4r+3
    unsigned long long acc[4][2] = {};

    #pragma unroll 2
    for (int k4 = 0; k4 < IN; k4 += 4) {
        float xv[4][4];
        #pragma unroll
        for (int i = 0; i < 4; i++)
            *(float4*)xv[i] = *(const float4*)&Xs[(4 * r + i) * IN + k4];
        #pragma unroll
        for (int kk = 0; kk < 4; kk++) {
            ulonglong2 w = *(const ulonglong2*)&Ws[(k4 + kk) * 64 + 4 * c];
            #pragma unroll
            for (int i = 0; i < 4; i++) {
                unsigned long long xd = dup2(xv[i][kk]);
                fma2(acc[i][0], xd, w.x);
                fma2(acc[i][1], xd, w.y);
            }
        }
    }

    float bg0 = bias_g[j0 + 4 * c + 0];
    float bg1 = bias_g[j0 + 4 * c + 1];
    float bg2 = bias_g[j0 + 4 * c + 2];
    float bg3 = bias_g[j0 + 4 * c + 3];
    #pragma unroll
    for (int i = 0; i < 4; i++) {
        int bt = bt0 + 4 * r + i;
        int b = bt >> 9;          // bt = b*T + t, T = 512
        int t = bt & (T - 1);
        float2 lo = unpack2(acc[i][0]);
        float2 hi = unpack2(acc[i][1]);
        float4 o = make_float4(lo.x + bg0, lo.y + bg1, hi.x + bg2, hi.y + bg3);
        *(float4*)&g_IG[((size_t)t * B + b) * H3 + j0 + 4 * c] = o;
    }
}

// ---------------------------------------------------------------------------
// Persistent GRU: all 512 timesteps in one launch. 128 CTAs (co-resident),
// CTA = (col-tile ct, row-block rb). W slab resident in smem for the whole
// kernel; per step: stage h via cp.async.cg (L2-coherent), prefetch IG,
// compute, epilogue, grid barrier.
// Thread = 1 row x 4 cols x 3 gates over all 256 k (6 u64 f32x2 accums).
// ---------------------------------------------------------------------------
__global__ __launch_bounds__(256) void gru_persistent(const float* __restrict__ bias_n) {
    extern __shared__ __align__(16) unsigned char smem_raw[];
    float* Wall = (float*)smem_raw;                        // [256][96]
    float* hs   = (float*)(smem_raw + WALL_BYTES);         // [32][256]

    const int tid = threadIdx.x;
    const int bx  = blockIdx.x;
    const int ct  = bx & 7;
    const int rb  = bx >> 3;
    const int r   = tid >> 3;        // row in tile, 0..31
    const int c   = tid & 7;         // 4-col quad
    const int row0 = rb * 32;
    const int row  = row0 + r;
    const int col  = ct * CTILE + 4 * c;

    uint32_t wall_s = (uint32_t)__cvta_generic_to_shared(Wall);
    uint32_t hs_s   = (uint32_t)__cvta_generic_to_shared(hs);

    // Load the whole W slab once (98304 B; 24 x cp16 per thread)
    {
        const float4* src = (const float4*)(g_Wpack + (size_t)ct * H * GC);
        #pragma unroll
        for (int j = 0; j < 24; j++) {
            int f = tid + j * 256;
            cp16(wall_s + f * 16, src + f);
        }
        cp_commit();
    }

    const float4 bn = *(const float4*)(bias_n + col);
    const float* wbase = Wall + 4 * c;
    const float4* hrow4 = (const float4*)(hs + r * H);

    for (int t = 0; t < T; t++) {
        const float* __restrict__ h_in  = g_h[t & 1];
        float* __restrict__ h_out       = g_h[(t + 1) & 1];

        // Stage h tile (32 x 256 contiguous floats) via cp.async.cg
        {
            const float4* src = (const float4*)(h_in + (size_t)row0 * H);
            #pragma unroll
            for (int i = 0; i < 8; i++) {
                int f = tid + i * 256;
                cp16(hs_s + f * 16, src + f);
            }
            cp_commit();
        }

        // Prefetch epilogue IG operands (DRAM): consumed after the k-loop
        const float* igp = g_IG + ((size_t)t * B + row) * H3 + col;
        float4 ir  = *(const float4*)(igp);
        float4 iz  = *(const float4*)(igp + H);
        float4 inn = *(const float4*)(igp + 2 * H);

        cp_wait0();            // t=0: also waits for W
        __syncthreads();

        unsigned long long aR0 = 0, aR1 = 0, aZ0 = 0, aZ1 = 0, aN0 = 0, aN1 = 0;

        #pragma unroll 4
        for (int k4i = 0; k4i < H / 4; k4i++) {        // 4 k's per iteration
            float4 hv = hrow4[k4i];
            unsigned long long hd[4];
            hd[0] = dup2(hv.x); hd[1] = dup2(hv.y);
            hd[2] = dup2(hv.z); hd[3] = dup2(hv.w);
            const float* wp = wbase + (k4i * 4) * GC;
            #pragma unroll
            for (int kk = 0; kk < 4; kk++) {
                ulonglong2 wR = *(const ulonglong2*)(wp);        // 128B bcast wf
                ulonglong2 wZ = *(const ulonglong2*)(wp + 32);
                ulonglong2 wN = *(const ulonglong2*)(wp + 64);
                fma2(aR0, hd[kk], wR.x); fma2(aR1, hd[kk], wR.y);
                fma2(aZ0, hd[kk], wZ.x); fma2(aZ1, hd[kk], wZ.y);
                fma2(aN0, hd[kk], wN.x); fma2(aN1, hd[kk], wN.y);
                wp += GC;
            }
        }

        // Epilogue: gates for 4 columns of one row
        float2 hrA = unpack2(aR0), hrB = unpack2(aR1);
        float2 hzA = unpack2(aZ0), hzB = unpack2(aZ1);
        float2 hnA = unpack2(aN0), hnB = unpack2(aN1);
        float4 hold = *(const float4*)&hs[r * H + col];

        float rg[4] = {ir.x + hrA.x, ir.y + hrA.y, ir.z + hrB.x, ir.w + hrB.y};
        float zg[4] = {iz.x + hzA.x, iz.y + hzA.y, iz.z + hzB.x, iz.w + hzB.y};
        float hnv[4] = {hnA.x, hnA.y, hnB.x, hnB.y};
        float igv[4] = {inn.x, inn.y, inn.z, inn.w};
        float bnv[4] = {bn.x, bn.y, bn.z, bn.w};
        float hov[4] = {hold.x, hold.y, hold.z, hold.w};

        float outv[4];
        #pragma unroll
        for (int i = 0; i < 4; i++) {
            float rv = sigmoidf_(rg[i]);
            float zv = sigmoidf_(zg[i]);
            float nv = tanhf_(igv[i] + rv * (hnv[i] + bnv[i]));
            outv[i] = nv + zv * (hov[i] - nv);
        }
        *(float4*)&h_out[(size_t)row * H + col] =
            make_float4(outv[0], outv[1], outv[2], outv[3]);

        // All CTAs' h_out visible before anyone stages the next h
        grid_barrier();
    }
}

// ---------------------------------------------------------------------------
// Final linear: out = h_final @ w_lin^T + bias_out (h_final in g_h[0])
// ---------------------------------------------------------------------------
__global__ __launch_bounds__(256) void final_linear(const float* __restrict__ bias_out,
                                                    float* __restrict__ out) {
    __shared__ float hsv[32 * H];
    int tid = threadIdx.x;
    int row0 = blockIdx.x * 32;
    {
        const float4* src = (const float4*)(g_h[0] + (size_t)row0 * H);
        float4* dst = (float4*)hsv;
        #pragma unroll
        for (int i = 0; i < 8; i++) dst[tid + i * 256] = src[tid + i * 256];
    }
    __syncthreads();

    int c = tid & 31;
    int r = tid >> 5;
    unsigned long long acc[4][2] = {};

    for (int k = 0; k < H; k++) {
        ulonglong2 w = *(const ulonglong2*)&g_WLt[k * OUT + 4 * c];
        #pragma unroll
        for (int i = 0; i < 4; i++) {
            unsigned long long hv = dup2(hsv[(4 * r + i) * H + k]);
            fma2(acc[i][0], hv, w.x);
            fma2(acc[i][1], hv, w.y);
        }
    }
    float b0 = bias_out[4 * c + 0];
    float b1 = bias_out[4 * c + 1];
    float b2 = bias_out[4 * c + 2];
    float b3 = bias_out[4 * c + 3];
    #pragma unroll
    for (int i = 0; i < 4; i++) {
        int row = row0 + 4 * r + i;
        float2 lo = unpack2(acc[i][0]);
        float2 hi = unpack2(acc[i][1]);
        float4 v = make_float4(lo.x + b0, lo.y + b1, hi.x + b2, hi.y + b3);
        *(float4*)&out[(size_t)row * OUT + 4 * c] = v;
    }
}

// ---------------------------------------------------------------------------
// Launch
// ---------------------------------------------------------------------------
extern "C" void kernel_launch(void* const* d_in, const int* in_sizes, int n_in,
                              void* d_out, int out_size) {
    const float* x        = (const float*)d_in[0];
    const float* w_ih     = (const float*)d_in[1];
    const float* w_hh     = (const float*)d_in[2];
    const float* bias_g   = (const float*)d_in[3];
    const float* bias_n   = (const float*)d_in[4];
    const float* w_lin    = (const float*)d_in[5];
    const float* bias_out = (const float*)d_in[6];
    float* out = (float*)d_out;
    (void)in_sizes; (void)n_in; (void)out_size;

    (void)cudaFuncSetAttribute(gru_persistent,
                               cudaFuncAttributeMaxDynamicSharedMemorySize,
                               SMEM_PERS);
    (void)cudaFuncSetAttribute(ig_gemm,
                               cudaFuncAttributeMaxDynamicSharedMemorySize,
                               SMEM_IG);

    prep_kernel<<<768, 256>>>(w_ih, w_hh, w_lin);

    dim3 gIG(H3 / 64, BT / 64);            // (12, 4096)
    ig_gemm<<<gIG, 256, SMEM_IG>>>(x, bias_g);

    gru_persistent<<<NBLK, 256, SMEM_PERS>>>(bias_n);

    final_linear<<<B / 32, 256>>>(bias_out, out);
}

// round 13
// speedup vs baseline: 2.5153x; 2.5153x over previous
#include <cuda_runtime.h>
#include <cuda_bf16.h>
#include <cstdint>
#include <cstddef>

// Problem dims
#define B   512
#define T   512
#define IN  128
#define H   256
#define H3  768
#define OUT 128
#define BT  (B * T)

// Persistent MMA tiling: 128 CTAs = 16 row-blocks x 8 col-tiles
#define NBLK  128
#define KPAD  264                       // padded k-row: 264 bf16 = 528 B (33 banks)
#define WROW_B (KPAD * 2)               // 528 bytes per k-row

// smem layout (bytes, from dynamic base)
#define W_HI_OFF 0
#define W_LO_OFF (96 * WROW_B)          // 50688
#define H_HI_OFF (2 * 96 * WROW_B)      // 101376
#define H_LO_OFF (H_HI_OFF + 32 * WROW_B) // 118272
#define SMEM_MMA (H_LO_OFF + 32 * WROW_B) // 135168

// ig_gemm dynamic smem
#define IG_XS_BYTES (64 * IN * 4)
#define IG_WS_BYTES (IN * 64 * 4)
#define SMEM_IG     (IG_XS_BYTES + IG_WS_BYTES)

// ---------------------------------------------------------------------------
// Static device scratch
// ---------------------------------------------------------------------------
__device__ float g_IG[(size_t)BT * H3];                   // input gates [t][b][j]
__device__ float g_WihT[IN * H3];                         // W_ih^T [k][j]
__device__ float g_WLt[H * OUT];                          // w_lin^T [k][o]
__device__ __align__(16) float g_h[2][B * H];             // fp32 hidden (ping-pong)
__device__ __align__(16) __nv_bfloat16 g_hhi[2][B * H];   // h hi split
__device__ __align__(16) __nv_bfloat16 g_hlo[2][B * H];   // h lo split
// W_hh bf16 splits, packed per col-tile: [nt][split][96 gate-cols][256 k]
__device__ __align__(16) __nv_bfloat16 g_Wpk[8 * 2 * 96 * 256];

// grid barrier
__device__ unsigned g_bar_count = 0;
__device__ volatile unsigned g_bar_gen = 0;

// ---------------------------------------------------------------------------
// helpers
// ---------------------------------------------------------------------------
__device__ __forceinline__ void fma2(unsigned long long &acc,
                                     unsigned long long a,
                                     unsigned long long b) {
    asm("fma.rn.f32x2 %0, %1, %2, %0;" : "+l"(acc) : "l"(a), "l"(b));
}
__device__ __forceinline__ unsigned long long dup2(float x) {
    unsigned long long r;
    asm("mov.b64 %0, {%1, %1};" : "=l"(r) : "f"(x));
    return r;
}
__device__ __forceinline__ float2 unpack2(unsigned long long v) {
    float2 f;
    asm("mov.b64 {%0, %1}, %2;" : "=f"(f.x), "=f"(f.y) : "l"(v));
    return f;
}
__device__ __forceinline__ void cp16(uint32_t s, const void* g) {
    asm volatile("cp.async.cg.shared.global [%0], [%1], 16;" :: "r"(s), "l"(g));
}
__device__ __forceinline__ void cp_commit() { asm volatile("cp.async.commit_group;"); }
__device__ __forceinline__ void cp_wait0()  { asm volatile("cp.async.wait_group 0;"); }

__device__ __forceinline__ float sigmoidf_(float x) {
    return __fdividef(1.0f, 1.0f + __expf(-x));
}
__device__ __forceinline__ float tanhf_(float x) {
    return __fdividef(2.0f, 1.0f + __expf(-2.0f * x)) - 1.0f;
}

__device__ __forceinline__ void ldsm4(uint32_t &r0, uint32_t &r1, uint32_t &r2,
                                      uint32_t &r3, uint32_t addr) {
    asm volatile("ldmatrix.sync.aligned.m8n8.x4.shared.b16 {%0,%1,%2,%3}, [%4];"
                 : "=r"(r0), "=r"(r1), "=r"(r2), "=r"(r3) : "r"(addr));
}
__device__ __forceinline__ void ldsm2(uint32_t &r0, uint32_t &r1, uint32_t addr) {
    asm volatile("ldmatrix.sync.aligned.m8n8.x2.shared.b16 {%0,%1}, [%2];"
                 : "=r"(r0), "=r"(r1) : "r"(addr));
}
__device__ __forceinline__ void mma_bf16(float* d, const uint32_t* a,
                                         const uint32_t* b) {
    asm volatile(
        "mma.sync.aligned.m16n8k16.row.col.f32.bf16.bf16.f32 "
        "{%0,%1,%2,%3}, {%4,%5,%6,%7}, {%8,%9}, {%0,%1,%2,%3};"
        : "+f"(d[0]), "+f"(d[1]), "+f"(d[2]), "+f"(d[3])
        : "r"(a[0]), "r"(a[1]), "r"(a[2]), "r"(a[3]), "r"(b[0]), "r"(b[1]));
}

// All-CTA barrier (NBLK co-resident CTAs: 128 <= 148 SMs, 1 CTA/SM at 135KB smem)
__device__ __forceinline__ void grid_barrier() {
    __syncthreads();
    if (threadIdx.x == 0) {
        __threadfence();
        unsigned gen = g_bar_gen;
        if (atomicAdd(&g_bar_count, 1u) == NBLK - 1u) {
            g_bar_count = 0;
            __threadfence();
            g_bar_gen = gen + 1u;
        } else {
            while (g_bar_gen == gen) { __nanosleep(64); }
        }
    }
    __syncthreads();
}

// ---------------------------------------------------------------------------
// Prep: transposes, W_hh bf16 hi/lo packing, h0/h-split zeros.
// ---------------------------------------------------------------------------
__global__ void prep_kernel(const float* __restrict__ w_ih,
                            const float* __restrict__ w_hh,
                            const float* __restrict__ w_lin) {
    int i = blockIdx.x * blockDim.x + threadIdx.x;
    if (i < IN * H3) {                       // w_ih: (H3, IN) -> [k][j]
        int j = i / IN, k = i % IN;
        g_WihT[k * H3 + j] = w_ih[i];
    }
    if (i < 8 * 96 * 256) {                  // W_hh -> per-tile bf16 splits
        int k   = i & 255;
        int tc  = (i >> 8) % 96;             // gate-col within tile: g*32+cc
        int nt  = i / (96 * 256);
        int g   = tc >> 5, cc = tc & 31;
        float v = w_hh[(size_t)(g * H + nt * 32 + cc) * H + k];
        __nv_bfloat16 hi = __float2bfloat16(v);
        __nv_bfloat16 lo = __float2bfloat16(v - __bfloat162float(hi));
        g_Wpk[((size_t)(nt * 2 + 0) * 96 + tc) * 256 + k] = hi;
        g_Wpk[((size_t)(nt * 2 + 1) * 96 + tc) * 256 + k] = lo;
    }
    if (i < OUT * H) {                       // w_lin: (OUT, H) -> [k][o]
        int o = i / H, k = i % H;
        g_WLt[k * OUT + o] = w_lin[i];
    }
    if (i < B * H) {
        g_h[0][i] = 0.0f;
        g_hhi[0][i] = __float2bfloat16(0.0f);
        g_hlo[0][i] = __float2bfloat16(0.0f);
    }
    if (i == 0) g_bar_count = 0;
}

// ---------------------------------------------------------------------------
// IG GEMM (SIMT f32x2): g_IG[t][b][j] = x . w_ih^T + bias_g
// ---------------------------------------------------------------------------
__global__ __launch_bounds__(256) void ig_gemm(const float* __restrict__ x,
                                               const float* __restrict__ bias_g) {
    extern __shared__ __align__(16) unsigned char ig_smem[];
    float* Xs = (float*)ig_smem;
    float* Ws = (float*)(ig_smem + IG_XS_BYTES);

    int tid = threadIdx.x;
    int bt0 = blockIdx.y * 64;
    int j0  = blockIdx.x * 64;

    {
        const float4* src = (const float4*)(x + (size_t)bt0 * IN);
        float4* dst = (float4*)Xs;
        #pragma unroll
        for (int i = 0; i < 8; i++) dst[tid + i * 256] = src[tid + i * 256];
    }
    {
        #pragma unroll
        for (int i = 0; i < 8; i++) {
            int f = tid + i * 256;
            int k = f >> 4, j4 = (f & 15) << 2;
            *(float4*)&Ws[k * 64 + j4] = *(const float4*)&g_WihT[k * H3 + j0 + j4];
        }
    }
    __syncthreads();

    int c = tid & 15;
    int r = tid >> 4;
    unsigned long long acc[4][2] = {};

    #pragma unroll 2
    for (int k4 = 0; k4 < IN; k4 += 4) {
        float xv[4][4];
        #pragma unroll
        for (int i = 0; i < 4; i++)
            *(float4*)xv[i] = *(const float4*)&Xs[(4 * r + i) * IN + k4];
        #pragma unroll
        for (int kk = 0; kk < 4; kk++) {
            ulonglong2 w = *(const ulonglong2*)&Ws[(k4 + kk) * 64 + 4 * c];
            #pragma unroll
            for (int i = 0; i < 4; i++) {
                unsigned long long xd = dup2(xv[i][kk]);
                fma2(acc[i][0], xd, w.x);
                fma2(acc[i][1], xd, w.y);
            }
        }
    }

    float bg0 = bias_g[j0 + 4 * c + 0];
    float bg1 = bias_g[j0 + 4 * c + 1];
    float bg2 = bias_g[j0 + 4 * c + 2];
    float bg3 = bias_g[j0 + 4 * c + 3];
    #pragma unroll
    for (int i = 0; i < 4; i++) {
        int bt = bt0 + 4 * r + i;
        int b = bt >> 9;
        int t = bt & (T - 1);
        float2 lo = unpack2(acc[i][0]);
        float2 hi = unpack2(acc[i][1]);
        float4 o = make_float4(lo.x + bg0, lo.y + bg1, hi.x + bg2, hi.y + bg3);
        *(float4*)&g_IG[((size_t)t * B + b) * H3 + j0 + 4 * c] = o;
    }
}

// ---------------------------------------------------------------------------
// Persistent HMMA GRU. 128 CTAs: mt = bx>>3 (32-row block), nt = bx&7 (32 h-cols
// = 96 gate-cols [r|z|n]). Warp w: m-half = w>>2 (16 rows), q = w&3 (8 h-cols);
// computes D n-tiles (q, q+4, q+8) so each thread's fragments hold matched
// (hr,hz,hn). Per step: D = h_hi.W_hi + h_hi.W_lo + h_lo.W_hi (bf16x3).
// ---------------------------------------------------------------------------
__global__ __launch_bounds__(256)
void gru_mma(const float* __restrict__ bias_n) {
    extern __shared__ __align__(16) unsigned char smraw[];
    uint32_t base_s = (uint32_t)__cvta_generic_to_shared(smraw);
    uint32_t whi_s = base_s + W_HI_OFF;
    uint32_t wlo_s = base_s + W_LO_OFF;
    uint32_t hhi_s = base_s + H_HI_OFF;
    uint32_t hlo_s = base_s + H_LO_OFF;

    const int tid = threadIdx.x;
    const int w   = tid >> 5;
    const int l   = tid & 31;
    const int nt  = blockIdx.x & 7;
    const int mt  = blockIdx.x >> 3;
    const int row0 = mt * 32;
    const int mhalf = w >> 2;        // 0/1: rows 0-15 / 16-31 of tile
    const int q     = w & 3;         // 8-h-col group

    // One-time: stage W hi/lo tile into padded smem rows (6144 cp16)
    {
        const __nv_bfloat16* src0 = g_Wpk + (size_t)(nt * 2) * 96 * 256;
        #pragma unroll
        for (int j = 0; j < 24; j++) {
            int f = tid + j * 256;               // 0..6143
            int split = f / 3072;
            int rem = f - split * 3072;
            int tc = rem >> 5, c = rem & 31;
            uint32_t dst = (split ? wlo_s : whi_s) + tc * WROW_B + c * 16;
            cp16(dst, src0 + ((size_t)split * 96 + tc) * 256 + c * 8);
        }
        cp_commit();
    }

    // ldmatrix lane addresses (byte offsets within padded tiles)
    const int aRow = mhalf * 16 + (l & 7) + ((l >> 3) & 1) * 8;
    const int aKh  = l >> 4;
    const uint32_t aOffB = (uint32_t)aRow * WROW_B + aKh * 16;
    const int l16 = l & 15;
    const uint32_t bRowOff = (uint32_t)(l16 & 7) * WROW_B + (l16 >> 3) * 16;

    // epilogue coordinates
    const int jcol = nt * 32 + q * 8 + (l & 3) * 2;     // global h-col (pair)
    const int r0g  = row0 + mhalf * 16 + (l >> 2);      // global row
    const int r1g  = r0g + 8;
    const float2 bn = *(const float2*)(bias_n + jcol);

    for (int t = 0; t < T; t++) {
        if (t) grid_barrier();       // h(t) stores visible chip-wide

        // Stage h hi/lo tile (2048 cp16)
        {
            const __nv_bfloat16* shi = g_hhi[t & 1] + (size_t)row0 * H;
            const __nv_bfloat16* slo = g_hlo[t & 1] + (size_t)row0 * H;
            #pragma unroll
            for (int j = 0; j < 8; j++) {
                int f = tid + j * 256;           // 0..2047
                int split = f >> 10;
                int rem = f & 1023;
                int rr = rem >> 5, c = rem & 31;
                uint32_t dst = (split ? hlo_s : hhi_s) + rr * WROW_B + c * 16;
                const __nv_bfloat16* s = (split ? slo : shi) + rr * H + c * 8;
                cp16(dst, s);
            }
            cp_commit();
        }

        // Prefetch epilogue operands (overlaps with cp.async + MMA)
        const float* igb = g_IG + (size_t)t * B * H3;
        float2 ir0 = *(const float2*)(igb + (size_t)r0g * H3 + jcol);
        float2 ir1 = *(const float2*)(igb + (size_t)r1g * H3 + jcol);
        float2 iz0 = *(const float2*)(igb + (size_t)r0g * H3 + H + jcol);
        float2 iz1 = *(const float2*)(igb + (size_t)r1g * H3 + H + jcol);
        float2 in0 = *(const float2*)(igb + (size_t)r0g * H3 + 2 * H + jcol);
        float2 in1 = *(const float2*)(igb + (size_t)r1g * H3 + 2 * H + jcol);
        float2 ho0 = *(const float2*)(g_h[t & 1] + (size_t)r0g * H + jcol);
        float2 ho1 = *(const float2*)(g_h[t & 1] + (size_t)r1g * H + jcol);

        cp_wait0();                  // t=0 also waits for W
        __syncthreads();

        float accR[4] = {0.f, 0.f, 0.f, 0.f};
        float accZ[4] = {0.f, 0.f, 0.f, 0.f};
        float accN[4] = {0.f, 0.f, 0.f, 0.f};

        #pragma unroll
        for (int ks = 0; ks < 16; ks++) {
            const uint32_t kByte = (uint32_t)ks * 32;
            uint32_t ahi[4], alo[4];
            ldsm4(ahi[0], ahi[1], ahi[2], ahi[3], hhi_s + aOffB + kByte);
            ldsm4(alo[0], alo[1], alo[2], alo[3], hlo_s + aOffB + kByte);

            #pragma unroll
            for (int g = 0; g < 3; g++) {
                const uint32_t tcBase = (uint32_t)(g * 32 + q * 8) * WROW_B;
                uint32_t bhi[2], blo[2];
                ldsm2(bhi[0], bhi[1], whi_s + tcBase + bRowOff + kByte);
                ldsm2(blo[0], blo[1], wlo_s + tcBase + bRowOff + kByte);
                float* acc = (g == 0) ? accR : (g == 1) ? accZ : accN;
                mma_bf16(acc, ahi, bhi);
                mma_bf16(acc, ahi, blo);
                mma_bf16(acc, alo, bhi);
            }
        }

        // Gate epilogue (register-local): rows r0g (acc[0],acc[1]) and r1g
        float rv0x = sigmoidf_(ir0.x + accR[0]);
        float rv0y = sigmoidf_(ir0.y + accR[1]);
        float rv1x = sigmoidf_(ir1.x + accR[2]);
        float rv1y = sigmoidf_(ir1.y + accR[3]);
        float zv0x = sigmoidf_(iz0.x + accZ[0]);
        float zv0y = sigmoidf_(iz0.y + accZ[1]);
        float zv1x = sigmoidf_(iz1.x + accZ[2]);
        float zv1y = sigmoidf_(iz1.y + accZ[3]);
        float nv0x = tanhf_(in0.x + rv0x * (accN[0] + bn.x));
        float nv0y = tanhf_(in0.y + rv0y * (accN[1] + bn.y));
        float nv1x = tanhf_(in1.x + rv1x * (accN[2] + bn.x));
        float nv1y = tanhf_(in1.y + rv1y * (accN[3] + bn.y));

        float2 h0, h1;
        h0.x = nv0x + zv0x * (ho0.x - nv0x);
        h0.y = nv0y + zv0y * (ho0.y - nv0y);
        h1.x = nv1x + zv1x * (ho1.x - nv1x);
        h1.y = nv1y + zv1y * (ho1.y - nv1y);

        // Store h fp32 + bf16 splits for t+1
        float* hOut = g_h[(t + 1) & 1];
        __nv_bfloat16* hhiOut = g_hhi[(t + 1) & 1];
        __nv_bfloat16* hloOut = g_hlo[(t + 1) & 1];
        *(float2*)(hOut + (size_t)r0g * H + jcol) = h0;
        *(float2*)(hOut + (size_t)r1g * H + jcol) = h1;

        __nv_bfloat162 p0h, p0l, p1h, p1l;
        p0h.x = __float2bfloat16(h0.x);  p0h.y = __float2bfloat16(h0.y);
        p0l.x = __float2bfloat16(h0.x - __bfloat162float(p0h.x));
        p0l.y = __float2bfloat16(h0.y - __bfloat162float(p0h.y));
        p1h.x = __float2bfloat16(h1.x);  p1h.y = __float2bfloat16(h1.y);
        p1l.x = __float2bfloat16(h1.x - __bfloat162float(p1h.x));
        p1l.y = __float2bfloat16(h1.y - __bfloat162float(p1h.y));
        *(__nv_bfloat162*)(hhiOut + (size_t)r0g * H + jcol) = p0h;
        *(__nv_bfloat162*)(hloOut + (size_t)r0g * H + jcol) = p0l;
        *(__nv_bfloat162*)(hhiOut + (size_t)r1g * H + jcol) = p1h;
        *(__nv_bfloat162*)(hloOut + (size_t)r1g * H + jcol) = p1l;
    }
}

// ---------------------------------------------------------------------------
// Final linear: out = h_final @ w_lin^T + bias_out (h_final in g_h[0])
// ---------------------------------------------------------------------------
__global__ __launch_bounds__(256) void final_linear(const float* __restrict__ bias_out,
                                                    float* __restrict__ out) {
    __shared__ float hsv[32 * H];
    int tid = threadIdx.x;
    int row0 = blockIdx.x * 32;
    {
        const float4* src = (const float4*)(g_h[0] + (size_t)row0 * H);
        float4* dst = (float4*)hsv;
        #pragma unroll
        for (int i = 0; i < 8; i++) dst[tid + i * 256] = src[tid + i * 256];
    }
    __syncthreads();

    int c = tid & 31;
    int r = tid >> 5;
    unsigned long long acc[4][2] = {};

    for (int k = 0; k < H; k++) {
        ulonglong2 w = *(const ulonglong2*)&g_WLt[k * OUT + 4 * c];
        #pragma unroll
        for (int i = 0; i < 4; i++) {
            unsigned long long hv = dup2(hsv[(4 * r + i) * H + k]);
            fma2(acc[i][0], hv, w.x);
            fma2(acc[i][1], hv, w.y);
        }
    }
    float b0 = bias_out[4 * c + 0];
    float b1 = bias_out[4 * c + 1];
    float b2 = bias_out[4 * c + 2];
    float b3 = bias_out[4 * c + 3];
    #pragma unroll
    for (int i = 0; i < 4; i++) {
        int row = row0 + 4 * r + i;
        float2 lo = unpack2(acc[i][0]);
        float2 hi = unpack2(acc[i][1]);
        float4 v = make_float4(lo.x + b0, lo.y + b1, hi.x + b2, hi.y + b3);
        *(float4*)&out[(size_t)row * OUT + 4 * c] = v;
    }
}

// ---------------------------------------------------------------------------
// Launch
// ---------------------------------------------------------------------------
extern "C" void kernel_launch(void* const* d_in, const int* in_sizes, int n_in,
                              void* d_out, int out_size) {
    const float* x        = (const float*)d_in[0];
    const float* w_ih     = (const float*)d_in[1];
    const float* w_hh     = (const float*)d_in[2];
    const float* bias_g   = (const float*)d_in[3];
    const float* bias_n   = (const float*)d_in[4];
    const float* w_lin    = (const float*)d_in[5];
    const float* bias_out = (const float*)d_in[6];
    float* out = (float*)d_out;
    (void)in_sizes; (void)n_in; (void)out_size;

    (void)cudaFuncSetAttribute(gru_mma,
                               cudaFuncAttributeMaxDynamicSharedMemorySize,
                               SMEM_MMA);
    (void)cudaFuncSetAttribute(ig_gemm,
                               cudaFuncAttributeMaxDynamicSharedMemorySize,
                               SMEM_IG);

    prep_kernel<<<1536, 256>>>(w_ih, w_hh, w_lin);

    dim3 gIG(H3 / 64, BT / 64);
    ig_gemm<<<gIG, 256, SMEM_IG>>>(x, bias_g);

    gru_mma<<<NBLK, 256, SMEM_MMA>>>(bias_n);

    final_linear<<<B / 32, 256>>>(bias_out, out);
}

// round 14
// speedup vs baseline: 3.3826x; 1.3448x over previous
#include <cuda_runtime.h>
#include <cuda_bf16.h>
#include <cstdint>
#include <cstddef>

// Problem dims
#define B   512
#define T   512
#define IN  128
#define H   256
#define H3  768
#define OUT 128
#define BT  (B * T)

// Persistent MMA tiling: 128 CTAs = 16 row-blocks x 8 col-tiles
#define NBLK  128
#define WROW_B 528                      // padded 256-k row: 264 bf16 (h / W_hh)
#define XROW_B 272                      // padded 128-k row: 136 bf16 (x / W_ih)

// smem layout (bytes, from dynamic base; all offsets 16B-aligned)
#define WHH_HI_OFF 0
#define WHH_LO_OFF (96 * WROW_B)                    // 50688
#define WIH_HI_OFF (2 * 96 * WROW_B)                // 101376
#define WIH_LO_OFF (WIH_HI_OFF + 96 * XROW_B)       // 127488
#define H_HI_OFF   (WIH_LO_OFF + 96 * XROW_B)       // 153600
#define H_LO_OFF   (H_HI_OFF + 32 * WROW_B)         // 170496
#define X_HI_OFF   (H_LO_OFF + 32 * WROW_B)         // 187392
#define X_LO_OFF   (X_HI_OFF + 32 * XROW_B)         // 196096
#define SMEM_MMA   (X_LO_OFF + 32 * XROW_B)         // 204800

// ---------------------------------------------------------------------------
// Static device scratch
// ---------------------------------------------------------------------------
__device__ float g_WLt[H * OUT];                          // w_lin^T [k][o]
__device__ __align__(16) float g_h[2][B * H];             // fp32 hidden (ping-pong)
__device__ __align__(16) __nv_bfloat16 g_hhi[2][B * H];   // h hi split
__device__ __align__(16) __nv_bfloat16 g_hlo[2][B * H];   // h lo split
__device__ __align__(16) __nv_bfloat16 g_xhi[(size_t)BT * IN];  // x hi split
__device__ __align__(16) __nv_bfloat16 g_xlo[(size_t)BT * IN];  // x lo split
// W_hh bf16 splits: [nt][split][96 gate-cols][256 k]
__device__ __align__(16) __nv_bfloat16 g_Wpk[8 * 2 * 96 * 256];
// W_ih bf16 splits: [nt][split][96 gate-cols][128 k]
__device__ __align__(16) __nv_bfloat16 g_WihPk[8 * 2 * 96 * 128];

// grid barrier
__device__ unsigned g_bar_count = 0;
__device__ volatile unsigned g_bar_gen = 0;

// ---------------------------------------------------------------------------
// helpers
// ---------------------------------------------------------------------------
__device__ __forceinline__ void fma2(unsigned long long &acc,
                                     unsigned long long a,
                                     unsigned long long b) {
    asm("fma.rn.f32x2 %0, %1, %2, %0;" : "+l"(acc) : "l"(a), "l"(b));
}
__device__ __forceinline__ unsigned long long dup2(float x) {
    unsigned long long r;
    asm("mov.b64 %0, {%1, %1};" : "=l"(r) : "f"(x));
    return r;
}
__device__ __forceinline__ float2 unpack2(unsigned long long v) {
    float2 f;
    asm("mov.b64 {%0, %1}, %2;" : "=f"(f.x), "=f"(f.y) : "l"(v));
    return f;
}
__device__ __forceinline__ void cp16(uint32_t s, const void* g) {
    asm volatile("cp.async.cg.shared.global [%0], [%1], 16;" :: "r"(s), "l"(g));
}
__device__ __forceinline__ void cp_commit() { asm volatile("cp.async.commit_group;"); }
__device__ __forceinline__ void cp_wait0()  { asm volatile("cp.async.wait_group 0;"); }

__device__ __forceinline__ float sigmoidf_(float x) {
    return __fdividef(1.0f, 1.0f + __expf(-x));
}
__device__ __forceinline__ float tanhf_(float x) {
    return __fdividef(2.0f, 1.0f + __expf(-2.0f * x)) - 1.0f;
}

__device__ __forceinline__ void ldsm4(uint32_t &r0, uint32_t &r1, uint32_t &r2,
                                      uint32_t &r3, uint32_t addr) {
    asm volatile("ldmatrix.sync.aligned.m8n8.x4.shared.b16 {%0,%1,%2,%3}, [%4];"
                 : "=r"(r0), "=r"(r1), "=r"(r2), "=r"(r3) : "r"(addr));
}
__device__ __forceinline__ void ldsm2(uint32_t &r0, uint32_t &r1, uint32_t addr) {
    asm volatile("ldmatrix.sync.aligned.m8n8.x2.shared.b16 {%0,%1}, [%2];"
                 : "=r"(r0), "=r"(r1) : "r"(addr));
}
__device__ __forceinline__ void mma_bf16(float* d, const uint32_t* a,
                                         const uint32_t* b) {
    asm volatile(
        "mma.sync.aligned.m16n8k16.row.col.f32.bf16.bf16.f32 "
        "{%0,%1,%2,%3}, {%4,%5,%6,%7}, {%8,%9}, {%0,%1,%2,%3};"
        : "+f"(d[0]), "+f"(d[1]), "+f"(d[2]), "+f"(d[3])
        : "r"(a[0]), "r"(a[1]), "r"(a[2]), "r"(a[3]), "r"(b[0]), "r"(b[1]));
}

// ---------------------------------------------------------------------------
// split_x: x fp32 -> bf16 hi/lo images (one-shot)
// ---------------------------------------------------------------------------
__global__ __launch_bounds__(256) void split_x(const float* __restrict__ x) {
    size_t i = (size_t)blockIdx.x * 256 + threadIdx.x;   // float4 index
    if (i >= (size_t)BT * IN / 4) return;
    float4 v = ((const float4*)x)[i];
    __nv_bfloat162 h01, h23, l01, l23;
    h01.x = __float2bfloat16(v.x); h01.y = __float2bfloat16(v.y);
    h23.x = __float2bfloat16(v.z); h23.y = __float2bfloat16(v.w);
    l01.x = __float2bfloat16(v.x - __bfloat162float(h01.x));
    l01.y = __float2bfloat16(v.y - __bfloat162float(h01.y));
    l23.x = __float2bfloat16(v.z - __bfloat162float(h23.x));
    l23.y = __float2bfloat16(v.w - __bfloat162float(h23.y));
    *(__nv_bfloat162*)(g_xhi + i * 4)     = h01;
    *(__nv_bfloat162*)(g_xhi + i * 4 + 2) = h23;
    *(__nv_bfloat162*)(g_xlo + i * 4)     = l01;
    *(__nv_bfloat162*)(g_xlo + i * 4 + 2) = l23;
}

// ---------------------------------------------------------------------------
// Prep: W_hh + W_ih bf16 hi/lo packing, w_lin transpose, h0 zeros.
// ---------------------------------------------------------------------------
__global__ void prep_kernel(const float* __restrict__ w_ih,
                            const float* __restrict__ w_hh,
                            const float* __restrict__ w_lin) {
    int i = blockIdx.x * blockDim.x + threadIdx.x;
    if (i < 8 * 96 * 256) {                  // W_hh -> per-tile bf16 splits
        int k   = i & 255;
        int tc  = (i >> 8) % 96;             // gate-col within tile: g*32+cc
        int nt  = i / (96 * 256);
        int g   = tc >> 5, cc = tc & 31;
        float v = w_hh[(size_t)(g * H + nt * 32 + cc) * H + k];
        __nv_bfloat16 hi = __float2bfloat16(v);
        __nv_bfloat16 lo = __float2bfloat16(v - __bfloat162float(hi));
        g_Wpk[((size_t)(nt * 2 + 0) * 96 + tc) * 256 + k] = hi;
        g_Wpk[((size_t)(nt * 2 + 1) * 96 + tc) * 256 + k] = lo;
    }
    if (i < 8 * 96 * 128) {                  // W_ih -> per-tile bf16 splits
        int k   = i & 127;
        int tc  = (i >> 7) % 96;
        int nt  = i / (96 * 128);
        int g   = tc >> 5, cc = tc & 31;
        float v = w_ih[(size_t)(g * H + nt * 32 + cc) * IN + k];
        __nv_bfloat16 hi = __float2bfloat16(v);
        __nv_bfloat16 lo = __float2bfloat16(v - __bfloat162float(hi));
        g_WihPk[((size_t)(nt * 2 + 0) * 96 + tc) * 128 + k] = hi;
        g_WihPk[((size_t)(nt * 2 + 1) * 96 + tc) * 128 + k] = lo;
    }
    if (i < OUT * H) {                       // w_lin: (OUT, H) -> [k][o]
        int o = i / H, k = i % H;
        g_WLt[k * OUT + o] = w_lin[i];
    }
    if (i < B * H) {
        g_h[0][i] = 0.0f;
        g_hhi[0][i] = __float2bfloat16(0.0f);
        g_hlo[0][i] = __float2bfloat16(0.0f);
    }
    if (i == 0) g_bar_count = 0;
}

// ---------------------------------------------------------------------------
// Persistent fused HMMA GRU. 128 CTAs: mt = bx>>3 (32-row block), nt = bx&7
// (32 h-cols = 96 gate-cols [r|z|n]). Warp w: mhalf = w>>2 (16 rows),
// q = w&3 (8 h-cols). Per step:
//   x-phase (K=128):  accR/accZ/accNx += x_split @ W_ih_split (bf16x3)
//   h-phase (K=256):  accR/accZ/accNh += h_split @ W_hh_split (bf16x3)
//   epilogue: r=sig(accR+bgR), z=sig(accZ+bgZ),
//             n=tanh(accNx+bgN + r*(accNh+bn)), h'=n+z*(h_old-n)
// Grid barrier is split: arrive after stores, wait after x-phase.
// ---------------------------------------------------------------------------
__global__ __launch_bounds__(256)
void gru_mma(const __nv_bfloat16* __restrict__ dummy,
             const float* __restrict__ bias_g,
             const float* __restrict__ bias_n) {
    extern __shared__ __align__(16) unsigned char smraw[];
    uint32_t base_s = (uint32_t)__cvta_generic_to_shared(smraw);
    uint32_t whh_hi_s = base_s + WHH_HI_OFF;
    uint32_t whh_lo_s = base_s + WHH_LO_OFF;
    uint32_t wih_hi_s = base_s + WIH_HI_OFF;
    uint32_t wih_lo_s = base_s + WIH_LO_OFF;
    uint32_t hhi_s    = base_s + H_HI_OFF;
    uint32_t hlo_s    = base_s + H_LO_OFF;
    uint32_t xhi_s    = base_s + X_HI_OFF;
    uint32_t xlo_s    = base_s + X_LO_OFF;
    (void)dummy;

    const int tid = threadIdx.x;
    const int w   = tid >> 5;
    const int l   = tid & 31;
    const int nt  = blockIdx.x & 7;
    const int mt  = blockIdx.x >> 3;
    const int row0 = mt * 32;
    const int mhalf = w >> 2;
    const int q     = w & 3;

    // One-time: W_hh tile (6144 cp16) + W_ih tile (3072 cp16)
    {
        const __nv_bfloat16* src0 = g_Wpk + (size_t)(nt * 2) * 96 * 256;
        #pragma unroll
        for (int j = 0; j < 24; j++) {
            int f = tid + j * 256;               // 0..6143
            int split = f / 3072;
            int rem = f - split * 3072;
            int tc = rem >> 5, c = rem & 31;
            uint32_t dst = (split ? whh_lo_s : whh_hi_s) + tc * WROW_B + c * 16;
            cp16(dst, src0 + ((size_t)split * 96 + tc) * 256 + c * 8);
        }
        const __nv_bfloat16* src1 = g_WihPk + (size_t)(nt * 2) * 96 * 128;
        #pragma unroll
        for (int j = 0; j < 12; j++) {
            int f = tid + j * 256;               // 0..3071
            int split = f >> 11;                 // /1536 -> but 3072/2=1536; use div
            split = f / 1536;
            int rem = f - split * 1536;
            int tc = rem >> 4, c = rem & 15;
            uint32_t dst = (split ? wih_lo_s : wih_hi_s) + tc * XROW_B + c * 16;
            cp16(dst, src1 + ((size_t)split * 96 + tc) * 128 + c * 8);
        }
        cp_commit();
    }

    // ldmatrix lane addresses
    const int aRow = mhalf * 16 + (l & 7) + ((l >> 3) & 1) * 8;
    const int aKh  = l >> 4;
    const uint32_t aOffH = (uint32_t)aRow * WROW_B + aKh * 16;
    const uint32_t aOffX = (uint32_t)aRow * XROW_B + aKh * 16;
    const int l16 = l & 15;
    const uint32_t bOffH = (uint32_t)(l16 & 7) * WROW_B + (l16 >> 3) * 16;
    const uint32_t bOffX = (uint32_t)(l16 & 7) * XROW_B + (l16 >> 3) * 16;

    // epilogue coordinates
    const int jcol = nt * 32 + q * 8 + (l & 3) * 2;     // global h-col (pair)
    const int r0g  = row0 + mhalf * 16 + (l >> 2);      // global row
    const int r1g  = r0g + 8;
    const float2 bn  = *(const float2*)(bias_n + jcol);
    const float2 bgR = *(const float2*)(bias_g + jcol);
    const float2 bgZ = *(const float2*)(bias_g + H + jcol);
    const float2 bgN = *(const float2*)(bias_g + 2 * H + jcol);

    unsigned my_gen = 0;        // tid0-only barrier state
    int need_wait = 0;

    for (int t = 0; t < T; t++) {
        // ---- arrive (t>0): h(t) stores done in this CTA ----
        if (t) {
            __syncthreads();                 // all epilogue stores issued
            if (tid == 0) {
                __threadfence();
                my_gen = g_bar_gen;
                if (atomicAdd(&g_bar_count, 1u) == NBLK - 1u) {
                    g_bar_count = 0;
                    __threadfence();
                    g_bar_gen = my_gen + 1u;
                    need_wait = 0;
                } else {
                    need_wait = 1;
                }
            }
        }

        // ---- stage x(t) hi/lo (1024 cp16; independent of barrier) ----
        {
            #pragma unroll
            for (int j = 0; j < 4; j++) {
                int f = tid + j * 256;           // 0..1023
                int split = f >> 9;
                int rem = f & 511;
                int rr = rem >> 4, c = rem & 15;
                uint32_t dst = (split ? xlo_s : xhi_s) + rr * XROW_B + c * 16;
                const __nv_bfloat16* s =
                    (split ? g_xlo : g_xhi) +
                    ((size_t)(row0 + rr) * T + t) * IN + c * 8;
                cp16(dst, s);
            }
            cp_commit();
        }
        cp_wait0();              // t=0 also waits for W tiles
        __syncthreads();

        // ---- x-phase MMAs (hides barrier arrival of other CTAs) ----
        float accR[4] = {0.f, 0.f, 0.f, 0.f};
        float accZ[4] = {0.f, 0.f, 0.f, 0.f};
        float accNx[4] = {0.f, 0.f, 0.f, 0.f};
        float accNh[4] = {0.f, 0.f, 0.f, 0.f};

        #pragma unroll
        for (int ks = 0; ks < 8; ks++) {
            const uint32_t kByte = (uint32_t)ks * 32;
            uint32_t axh[4], axl[4];
            ldsm4(axh[0], axh[1], axh[2], axh[3], xhi_s + aOffX + kByte);
            ldsm4(axl[0], axl[1], axl[2], axl[3], xlo_s + aOffX + kByte);
            #pragma unroll
            for (int g = 0; g < 3; g++) {
                const uint32_t tcBase = (uint32_t)(g * 32 + q * 8) * XROW_B;
                uint32_t bh[2], bl[2];
                ldsm2(bh[0], bh[1], wih_hi_s + tcBase + bOffX + kByte);
                ldsm2(bl[0], bl[1], wih_lo_s + tcBase + bOffX + kByte);
                float* acc = (g == 0) ? accR : (g == 1) ? accZ : accNx;
                mma_bf16(acc, axh, bh);
                mma_bf16(acc, axh, bl);
                mma_bf16(acc, axl, bh);
            }
        }

        // ---- barrier wait (t>0): h(t) from all CTAs now visible ----
        if (t) {
            if (tid == 0 && need_wait) {
                while (g_bar_gen == my_gen) { __nanosleep(32); }
            }
            __syncthreads();
        }

        // ---- stage h(t) hi/lo (2048 cp16) + prefetch h_old ----
        {
            const __nv_bfloat16* shi = g_hhi[t & 1] + (size_t)row0 * H;
            const __nv_bfloat16* slo = g_hlo[t & 1] + (size_t)row0 * H;
            #pragma unroll
            for (int j = 0; j < 8; j++) {
                int f = tid + j * 256;           // 0..2047
                int split = f >> 10;
                int rem = f & 1023;
                int rr = rem >> 5, c = rem & 31;
                uint32_t dst = (split ? hlo_s : hhi_s) + rr * WROW_B + c * 16;
                const __nv_bfloat16* s = (split ? slo : shi) + rr * H + c * 8;
                cp16(dst, s);
            }
            cp_commit();
        }
        float2 ho0 = *(const float2*)(g_h[t & 1] + (size_t)r0g * H + jcol);
        float2 ho1 = *(const float2*)(g_h[t & 1] + (size_t)r1g * H + jcol);

        cp_wait0();
        __syncthreads();

        // ---- h-phase MMAs ----
        #pragma unroll
        for (int ks = 0; ks < 16; ks++) {
            const uint32_t kByte = (uint32_t)ks * 32;
            uint32_t ahi[4], alo[4];
            ldsm4(ahi[0], ahi[1], ahi[2], ahi[3], hhi_s + aOffH + kByte);
            ldsm4(alo[0], alo[1], alo[2], alo[3], hlo_s + aOffH + kByte);
            #pragma unroll
            for (int g = 0; g < 3; g++) {
                const uint32_t tcBase = (uint32_t)(g * 32 + q * 8) * WROW_B;
                uint32_t bh[2], bl[2];
                ldsm2(bh[0], bh[1], whh_hi_s + tcBase + bOffH + kByte);
                ldsm2(bl[0], bl[1], whh_lo_s + tcBase + bOffH + kByte);
                float* acc = (g == 0) ? accR : (g == 1) ? accZ : accNh;
                mma_bf16(acc, ahi, bh);
                mma_bf16(acc, ahi, bl);
                mma_bf16(acc, alo, bh);
            }
        }

        // ---- gate epilogue ----
        float rv0x = sigmoidf_(accR[0] + bgR.x);
        float rv0y = sigmoidf_(accR[1] + bgR.y);
        float rv1x = sigmoidf_(accR[2] + bgR.x);
        float rv1y = sigmoidf_(accR[3] + bgR.y);
        float zv0x = sigmoidf_(accZ[0] + bgZ.x);
        float zv0y = sigmoidf_(accZ[1] + bgZ.y);
        float zv1x = sigmoidf_(accZ[2] + bgZ.x);
        float zv1y = sigmoidf_(accZ[3] + bgZ.y);
        float nv0x = tanhf_(accNx[0] + bgN.x + rv0x * (accNh[0] + bn.x));
        float nv0y = tanhf_(accNx[1] + bgN.y + rv0y * (accNh[1] + bn.y));
        float nv1x = tanhf_(accNx[2] + bgN.x + rv1x * (accNh[2] + bn.x));
        float nv1y = tanhf_(accNx[3] + bgN.y + rv1y * (accNh[3] + bn.y));

        float2 h0, h1;
        h0.x = nv0x + zv0x * (ho0.x - nv0x);
        h0.y = nv0y + zv0y * (ho0.y - nv0y);
        h1.x = nv1x + zv1x * (ho1.x - nv1x);
        h1.y = nv1y + zv1y * (ho1.y - nv1y);

        // ---- store h fp32 + bf16 splits for t+1 ----
        float* hOut = g_h[(t + 1) & 1];
        __nv_bfloat16* hhiOut = g_hhi[(t + 1) & 1];
        __nv_bfloat16* hloOut = g_hlo[(t + 1) & 1];
        *(float2*)(hOut + (size_t)r0g * H + jcol) = h0;
        *(float2*)(hOut + (size_t)r1g * H + jcol) = h1;

        __nv_bfloat162 p0h, p0l, p1h, p1l;
        p0h.x = __float2bfloat16(h0.x);  p0h.y = __float2bfloat16(h0.y);
        p0l.x = __float2bfloat16(h0.x - __bfloat162float(p0h.x));
        p0l.y = __float2bfloat16(h0.y - __bfloat162float(p0h.y));
        p1h.x = __float2bfloat16(h1.x);  p1h.y = __float2bfloat16(h1.y);
        p1l.x = __float2bfloat16(h1.x - __bfloat162float(p1h.x));
        p1l.y = __float2bfloat16(h1.y - __bfloat162float(p1h.y));
        *(__nv_bfloat162*)(hhiOut + (size_t)r0g * H + jcol) = p0h;
        *(__nv_bfloat162*)(hloOut + (size_t)r0g * H + jcol) = p0l;
        *(__nv_bfloat162*)(hhiOut + (size_t)r1g * H + jcol) = p1h;
        *(__nv_bfloat162*)(hloOut + (size_t)r1g * H + jcol) = p1l;
    }
}

// ---------------------------------------------------------------------------
// Final linear: out = h_final @ w_lin^T + bias_out (h_final in g_h[0]).
// 128 CTAs x 128 thr; CTA = 4 rows, thread = 1 row x 4 cols.
// ---------------------------------------------------------------------------
__global__ __launch_bounds__(128) void final_linear(const float* __restrict__ bias_out,
                                                    float* __restrict__ out) {
    __shared__ float hsv[4 * H];
    int tid = threadIdx.x;
    int row0 = blockIdx.x * 4;
    {
        const float4* src = (const float4*)(g_h[0] + (size_t)row0 * H);
        float4* dst = (float4*)hsv;
        #pragma unroll
        for (int i = 0; i < 2; i++) dst[tid + i * 128] = src[tid + i * 128];
    }
    __syncthreads();

    int c = tid & 31;   // 4 cols: 4c..4c+3
    int r = tid >> 5;   // row 0..3
    unsigned long long acc[2] = {0ULL, 0ULL};

    #pragma unroll 4
    for (int k = 0; k < H; k++) {
        ulonglong2 wv = *(const ulonglong2*)&g_WLt[k * OUT + 4 * c];
        unsigned long long hv = dup2(hsv[r * H + k]);
        fma2(acc[0], hv, wv.x);
        fma2(acc[1], hv, wv.y);
    }
    float b0 = bias_out[4 * c + 0];
    float b1 = bias_out[4 * c + 1];
    float b2 = bias_out[4 * c + 2];
    float b3 = bias_out[4 * c + 3];
    float2 lo = unpack2(acc[0]);
    float2 hi = unpack2(acc[1]);
    float4 v = make_float4(lo.x + b0, lo.y + b1, hi.x + b2, hi.y + b3);
    *(float4*)&out[(size_t)(row0 + r) * OUT + 4 * c] = v;
}

// ---------------------------------------------------------------------------
// Launch
// ---------------------------------------------------------------------------
extern "C" void kernel_launch(void* const* d_in, const int* in_sizes, int n_in,
                              void* d_out, int out_size) {
    const float* x        = (const float*)d_in[0];
    const float* w_ih     = (const float*)d_in[1];
    const float* w_hh     = (const float*)d_in[2];
    const float* bias_g   = (const float*)d_in[3];
    const float* bias_n   = (const float*)d_in[4];
    const float* w_lin    = (const float*)d_in[5];
    const float* bias_out = (const float*)d_in[6];
    float* out = (float*)d_out;
    (void)in_sizes; (void)n_in; (void)out_size;

    (void)cudaFuncSetAttribute(gru_mma,
                               cudaFuncAttributeMaxDynamicSharedMemorySize,
                               SMEM_MMA);

    split_x<<<(BT * IN / 4 + 255) / 256, 256>>>(x);
    prep_kernel<<<768, 256>>>(w_ih, w_hh, w_lin);

    gru_mma<<<NBLK, 256, SMEM_MMA>>>(nullptr, bias_g, bias_n);

    final_linear<<<B / 4, 128>>>(bias_out, out);
}

// round 15
// speedup vs baseline: 3.3889x; 1.0019x over previous
#include <cuda_runtime.h>
#include <cuda_bf16.h>
#include <cstdint>
#include <cstddef>

// Problem dims
#define B   512
#define T   512
#define IN  128
#define H   256
#define H3  768
#define OUT 128
#define BT  (B * T)

// Persistent MMA tiling: 128 CTAs = 16 row-blocks x 8 col-tiles
#define NBLK  128
#define WROW_B 528                      // padded 256-k row: 264 bf16 (h / W_hh)
#define XROW_B 272                      // padded 128-k row: 136 bf16 (x / W_ih)

// smem layout (bytes, from dynamic base; all offsets 16B-aligned)
#define WHH_HI_OFF 0
#define WHH_LO_OFF (96 * WROW_B)                    // 50688
#define WIH_HI_OFF (2 * 96 * WROW_B)                // 101376
#define WIH_LO_OFF (WIH_HI_OFF + 96 * XROW_B)       // 127488
#define H_HI_OFF   (WIH_LO_OFF + 96 * XROW_B)       // 153600
#define H_LO_OFF   (H_HI_OFF + 32 * WROW_B)         // 170496
#define X_HI_OFF   (H_LO_OFF + 32 * WROW_B)         // 187392
#define X_LO_OFF   (X_HI_OFF + 32 * XROW_B)         // 196096
#define SMEM_MMA   (X_LO_OFF + 32 * XROW_B)         // 204800

// ---------------------------------------------------------------------------
// Static device scratch
// ---------------------------------------------------------------------------
__device__ float g_WLt[H * OUT];                          // w_lin^T [k][o]
__device__ __align__(16) float g_h[2][B * H];             // fp32 hidden (ping-pong)
__device__ __align__(16) __nv_bfloat16 g_hhi[2][B * H];   // h hi split
__device__ __align__(16) __nv_bfloat16 g_hlo[2][B * H];   // h lo split
__device__ __align__(16) __nv_bfloat16 g_xhi[(size_t)BT * IN];  // x hi split
__device__ __align__(16) __nv_bfloat16 g_xlo[(size_t)BT * IN];  // x lo split
// W_hh bf16 splits: [nt][split][96 gate-cols][256 k]
__device__ __align__(16) __nv_bfloat16 g_Wpk[8 * 2 * 96 * 256];
// W_ih bf16 splits: [nt][split][96 gate-cols][128 k]
__device__ __align__(16) __nv_bfloat16 g_WihPk[8 * 2 * 96 * 128];

// grid barrier
__device__ unsigned g_bar_count = 0;
__device__ volatile unsigned g_bar_gen = 0;

// ---------------------------------------------------------------------------
// helpers
// ---------------------------------------------------------------------------
__device__ __forceinline__ void fma2(unsigned long long &acc,
                                     unsigned long long a,
                                     unsigned long long b) {
    asm("fma.rn.f32x2 %0, %1, %2, %0;" : "+l"(acc) : "l"(a), "l"(b));
}
__device__ __forceinline__ unsigned long long dup2(float x) {
    unsigned long long r;
    asm("mov.b64 %0, {%1, %1};" : "=l"(r) : "f"(x));
    return r;
}
__device__ __forceinline__ float2 unpack2(unsigned long long v) {
    float2 f;
    asm("mov.b64 {%0, %1}, %2;" : "=f"(f.x), "=f"(f.y) : "l"(v));
    return f;
}
__device__ __forceinline__ void cp16(uint32_t s, const void* g) {
    asm volatile("cp.async.cg.shared.global [%0], [%1], 16;" :: "r"(s), "l"(g));
}
__device__ __forceinline__ void cp_commit() { asm volatile("cp.async.commit_group;"); }
__device__ __forceinline__ void cp_wait0()  { asm volatile("cp.async.wait_group 0;"); }

__device__ __forceinline__ float sigmoidf_(float x) {
    return __fdividef(1.0f, 1.0f + __expf(-x));
}
__device__ __forceinline__ float tanhf_(float x) {
    return __fdividef(2.0f, 1.0f + __expf(-2.0f * x)) - 1.0f;
}

__device__ __forceinline__ void ldsm4(uint32_t &r0, uint32_t &r1, uint32_t &r2,
                                      uint32_t &r3, uint32_t addr) {
    asm volatile("ldmatrix.sync.aligned.m8n8.x4.shared.b16 {%0,%1,%2,%3}, [%4];"
                 : "=r"(r0), "=r"(r1), "=r"(r2), "=r"(r3) : "r"(addr));
}
__device__ __forceinline__ void ldsm2(uint32_t &r0, uint32_t &r1, uint32_t addr) {
    asm volatile("ldmatrix.sync.aligned.m8n8.x2.shared.b16 {%0,%1}, [%2];"
                 : "=r"(r0), "=r"(r1) : "r"(addr));
}
__device__ __forceinline__ void mma_bf16(float* d, const uint32_t* a,
                                         const uint32_t* b) {
    asm volatile(
        "mma.sync.aligned.m16n8k16.row.col.f32.bf16.bf16.f32 "
        "{%0,%1,%2,%3}, {%4,%5,%6,%7}, {%8,%9}, {%0,%1,%2,%3};"
        : "+f"(d[0]), "+f"(d[1]), "+f"(d[2]), "+f"(d[3])
        : "r"(a[0]), "r"(a[1]), "r"(a[2]), "r"(a[3]), "r"(b[0]), "r"(b[1]));
}

// ---------------------------------------------------------------------------
// split_x: x fp32 -> bf16 hi/lo images (one-shot)
// ---------------------------------------------------------------------------
__global__ __launch_bounds__(256) void split_x(const float* __restrict__ x) {
    size_t i = (size_t)blockIdx.x * 256 + threadIdx.x;   // float4 index
    if (i >= (size_t)BT * IN / 4) return;
    float4 v = ((const float4*)x)[i];
    __nv_bfloat162 h01, h23, l01, l23;
    h01.x = __float2bfloat16(v.x); h01.y = __float2bfloat16(v.y);
    h23.x = __float2bfloat16(v.z); h23.y = __float2bfloat16(v.w);
    l01.x = __float2bfloat16(v.x - __bfloat162float(h01.x));
    l01.y = __float2bfloat16(v.y - __bfloat162float(h01.y));
    l23.x = __float2bfloat16(v.z - __bfloat162float(h23.x));
    l23.y = __float2bfloat16(v.w - __bfloat162float(h23.y));
    *(__nv_bfloat162*)(g_xhi + i * 4)     = h01;
    *(__nv_bfloat162*)(g_xhi + i * 4 + 2) = h23;
    *(__nv_bfloat162*)(g_xlo + i * 4)     = l01;
    *(__nv_bfloat162*)(g_xlo + i * 4 + 2) = l23;
}

// ---------------------------------------------------------------------------
// Prep: W_hh + W_ih bf16 hi/lo packing, w_lin transpose, h0 zeros.
// ---------------------------------------------------------------------------
__global__ void prep_kernel(const float* __restrict__ w_ih,
                            const float* __restrict__ w_hh,
                            const float* __restrict__ w_lin) {
    int i = blockIdx.x * blockDim.x + threadIdx.x;
    if (i < 8 * 96 * 256) {                  // W_hh -> per-tile bf16 splits
        int k   = i & 255;
        int tc  = (i >> 8) % 96;             // gate-col within tile: g*32+cc
        int nt  = i / (96 * 256);
        int g   = tc >> 5, cc = tc & 31;
        float v = w_hh[(size_t)(g * H + nt * 32 + cc) * H + k];
        __nv_bfloat16 hi = __float2bfloat16(v);
        __nv_bfloat16 lo = __float2bfloat16(v - __bfloat162float(hi));
        g_Wpk[((size_t)(nt * 2 + 0) * 96 + tc) * 256 + k] = hi;
        g_Wpk[((size_t)(nt * 2 + 1) * 96 + tc) * 256 + k] = lo;
    }
    if (i < 8 * 96 * 128) {                  // W_ih -> per-tile bf16 splits
        int k   = i & 127;
        int tc  = (i >> 7) % 96;
        int nt  = i / (96 * 128);
        int g   = tc >> 5, cc = tc & 31;
        float v = w_ih[(size_t)(g * H + nt * 32 + cc) * IN + k];
        __nv_bfloat16 hi = __float2bfloat16(v);
        __nv_bfloat16 lo = __float2bfloat16(v - __bfloat162float(hi));
        g_WihPk[((size_t)(nt * 2 + 0) * 96 + tc) * 128 + k] = hi;
        g_WihPk[((size_t)(nt * 2 + 1) * 96 + tc) * 128 + k] = lo;
    }
    if (i < OUT * H) {                       // w_lin: (OUT, H) -> [k][o]
        int o = i / H, k = i % H;
        g_WLt[k * OUT + o] = w_lin[i];
    }
    if (i < B * H) {
        g_h[0][i] = 0.0f;
        g_hhi[0][i] = __float2bfloat16(0.0f);
        g_hlo[0][i] = __float2bfloat16(0.0f);
    }
    if (i == 0) g_bar_count = 0;
}

// ---------------------------------------------------------------------------
// Persistent fused HMMA GRU. 128 CTAs: mt = bx>>3 (32-row block), nt = bx&7
// (32 h-cols = 96 gate-cols [r|z|n]). Warp w: mhalf = w>>2 (16 rows),
// q = w&3 (8 h-cols). Per step:
//   x-phase (K=128):  accR/accZ/accNx += x_split @ W_ih_split (bf16x3)
//   h-phase (K=256):  accR/accZ/accNh += h_split @ W_hh_split (bf16x3)
//   epilogue: r=sig(accR+bgR), z=sig(accZ+bgZ),
//             n=tanh(accNx+bgN + r*(accNh+bn)), h'=n+z*(h_old-n)
// Grid barrier is split: arrive after stores, wait after x-phase.
// ---------------------------------------------------------------------------
__global__ __launch_bounds__(256)
void gru_mma(const __nv_bfloat16* __restrict__ dummy,
             const float* __restrict__ bias_g,
             const float* __restrict__ bias_n) {
    extern __shared__ __align__(16) unsigned char smraw[];
    uint32_t base_s = (uint32_t)__cvta_generic_to_shared(smraw);
    uint32_t whh_hi_s = base_s + WHH_HI_OFF;
    uint32_t whh_lo_s = base_s + WHH_LO_OFF;
    uint32_t wih_hi_s = base_s + WIH_HI_OFF;
    uint32_t wih_lo_s = base_s + WIH_LO_OFF;
    uint32_t hhi_s    = base_s + H_HI_OFF;
    uint32_t hlo_s    = base_s + H_LO_OFF;
    uint32_t xhi_s    = base_s + X_HI_OFF;
    uint32_t xlo_s    = base_s + X_LO_OFF;
    (void)dummy;

    const int tid = threadIdx.x;
    const int w   = tid >> 5;
    const int l   = tid & 31;
    const int nt  = blockIdx.x & 7;
    const int mt  = blockIdx.x >> 3;
    const int row0 = mt * 32;
    const int mhalf = w >> 2;
    const int q     = w & 3;

    // One-time: W_hh tile (6144 cp16) + W_ih tile (3072 cp16)
    {
        const __nv_bfloat16* src0 = g_Wpk + (size_t)(nt * 2) * 96 * 256;
        #pragma unroll
        for (int j = 0; j < 24; j++) {
            int f = tid + j * 256;               // 0..6143
            int split = f / 3072;
            int rem = f - split * 3072;
            int tc = rem >> 5, c = rem & 31;
            uint32_t dst = (split ? whh_lo_s : whh_hi_s) + tc * WROW_B + c * 16;
            cp16(dst, src0 + ((size_t)split * 96 + tc) * 256 + c * 8);
        }
        const __nv_bfloat16* src1 = g_WihPk + (size_t)(nt * 2) * 96 * 128;
        #pragma unroll
        for (int j = 0; j < 12; j++) {
            int f = tid + j * 256;               // 0..3071
            int split = f >> 11;                 // /1536 -> but 3072/2=1536; use div
            split = f / 1536;
            int rem = f - split * 1536;
            int tc = rem >> 4, c = rem & 15;
            uint32_t dst = (split ? wih_lo_s : wih_hi_s) + tc * XROW_B + c * 16;
            cp16(dst, src1 + ((size_t)split * 96 + tc) * 128 + c * 8);
        }
        cp_commit();
    }

    // ldmatrix lane addresses
    const int aRow = mhalf * 16 + (l & 7) + ((l >> 3) & 1) * 8;
    const int aKh  = l >> 4;
    const uint32_t aOffH = (uint32_t)aRow * WROW_B + aKh * 16;
    const uint32_t aOffX = (uint32_t)aRow * XROW_B + aKh * 16;
    const int l16 = l & 15;
    const uint32_t bOffH = (uint32_t)(l16 & 7) * WROW_B + (l16 >> 3) * 16;
    const uint32_t bOffX = (uint32_t)(l16 & 7) * XROW_B + (l16 >> 3) * 16;

    // epilogue coordinates
    const int jcol = nt * 32 + q * 8 + (l & 3) * 2;     // global h-col (pair)
    const int r0g  = row0 + mhalf * 16 + (l >> 2);      // global row
    const int r1g  = r0g + 8;
    const float2 bn  = *(const float2*)(bias_n + jcol);
    const float2 bgR = *(const float2*)(bias_g + jcol);
    const float2 bgZ = *(const float2*)(bias_g + H + jcol);
    const float2 bgN = *(const float2*)(bias_g + 2 * H + jcol);

    unsigned my_gen = 0;        // tid0-only barrier state
    int need_wait = 0;

    for (int t = 0; t < T; t++) {
        // ---- arrive (t>0): h(t) stores done in this CTA ----
        if (t) {
            __syncthreads();                 // all epilogue stores issued
            if (tid == 0) {
                __threadfence();
                my_gen = g_bar_gen;
                if (atomicAdd(&g_bar_count, 1u) == NBLK - 1u) {
                    g_bar_count = 0;
                    __threadfence();
                    g_bar_gen = my_gen + 1u;
                    need_wait = 0;
                } else {
                    need_wait = 1;
                }
            }
        }

        // ---- stage x(t) hi/lo (1024 cp16; independent of barrier) ----
        {
            #pragma unroll
            for (int j = 0; j < 4; j++) {
                int f = tid + j * 256;           // 0..1023
                int split = f >> 9;
                int rem = f & 511;
                int rr = rem >> 4, c = rem & 15;
                uint32_t dst = (split ? xlo_s : xhi_s) + rr * XROW_B + c * 16;
                const __nv_bfloat16* s =
                    (split ? g_xlo : g_xhi) +
                    ((size_t)(row0 + rr) * T + t) * IN + c * 8;
                cp16(dst, s);
            }
            cp_commit();
        }
        cp_wait0();              // t=0 also waits for W tiles
        __syncthreads();

        // ---- x-phase MMAs (hides barrier arrival of other CTAs) ----
        float accR[4] = {0.f, 0.f, 0.f, 0.f};
        float accZ[4] = {0.f, 0.f, 0.f, 0.f};
        float accNx[4] = {0.f, 0.f, 0.f, 0.f};
        float accNh[4] = {0.f, 0.f, 0.f, 0.f};

        #pragma unroll
        for (int ks = 0; ks < 8; ks++) {
            const uint32_t kByte = (uint32_t)ks * 32;
            uint32_t axh[4], axl[4];
            ldsm4(axh[0], axh[1], axh[2], axh[3], xhi_s + aOffX + kByte);
            ldsm4(axl[0], axl[1], axl[2], axl[3], xlo_s + aOffX + kByte);
            #pragma unroll
            for (int g = 0; g < 3; g++) {
                const uint32_t tcBase = (uint32_t)(g * 32 + q * 8) * XROW_B;
                uint32_t bh[2], bl[2];
                ldsm2(bh[0], bh[1], wih_hi_s + tcBase + bOffX + kByte);
                ldsm2(bl[0], bl[1], wih_lo_s + tcBase + bOffX + kByte);
                float* acc = (g == 0) ? accR : (g == 1) ? accZ : accNx;
                mma_bf16(acc, axh, bh);
                mma_bf16(acc, axh, bl);
                mma_bf16(acc, axl, bh);
            }
        }

        // ---- barrier wait (t>0): h(t) from all CTAs now visible ----
        if (t) {
            if (tid == 0 && need_wait) {
                while (g_bar_gen == my_gen) { __nanosleep(32); }
            }
            __syncthreads();
        }

        // ---- stage h(t) hi/lo (2048 cp16) + prefetch h_old ----
        {
            const __nv_bfloat16* shi = g_hhi[t & 1] + (size_t)row0 * H;
            const __nv_bfloat16* slo = g_hlo[t & 1] + (size_t)row0 * H;
            #pragma unroll
            for (int j = 0; j < 8; j++) {
                int f = tid + j * 256;           // 0..2047
                int split = f >> 10;
                int rem = f & 1023;
                int rr = rem >> 5, c = rem & 31;
                uint32_t dst = (split ? hlo_s : hhi_s) + rr * WROW_B + c * 16;
                const __nv_bfloat16* s = (split ? slo : shi) + rr * H + c * 8;
                cp16(dst, s);
            }
            cp_commit();
        }
        float2 ho0 = *(const float2*)(g_h[t & 1] + (size_t)r0g * H + jcol);
        float2 ho1 = *(const float2*)(g_h[t & 1] + (size_t)r1g * H + jcol);

        cp_wait0();
        __syncthreads();

        // ---- h-phase MMAs ----
        #pragma unroll
        for (int ks = 0; ks < 16; ks++) {
            const uint32_t kByte = (uint32_t)ks * 32;
            uint32_t ahi[4], alo[4];
            ldsm4(ahi[0], ahi[1], ahi[2], ahi[3], hhi_s + aOffH + kByte);
            ldsm4(alo[0], alo[1], alo[2], alo[3], hlo_s + aOffH + kByte);
            #pragma unroll
            for (int g = 0; g < 3; g++) {
                const uint32_t tcBase = (uint32_t)(g * 32 + q * 8) * WROW_B;
                uint32_t bh[2], bl[2];
                ldsm2(bh[0], bh[1], whh_hi_s + tcBase + bOffH + kByte);
                ldsm2(bl[0], bl[1], whh_lo_s + tcBase + bOffH + kByte);
                float* acc = (g == 0) ? accR : (g == 1) ? accZ : accNh;
                mma_bf16(acc, ahi, bh);
                mma_bf16(acc, ahi, bl);
                mma_bf16(acc, alo, bh);
            }
        }

        // ---- gate epilogue ----
        float rv0x = sigmoidf_(accR[0] + bgR.x);
        float rv0y = sigmoidf_(accR[1] + bgR.y);
        float rv1x = sigmoidf_(accR[2] + bgR.x);
        float rv1y = sigmoidf_(accR[3] + bgR.y);
        float zv0x = sigmoidf_(accZ[0] + bgZ.x);
        float zv0y = sigmoidf_(accZ[1] + bgZ.y);
        float zv1x = sigmoidf_(accZ[2] + bgZ.x);
        float zv1y = sigmoidf_(accZ[3] + bgZ.y);
        float nv0x = tanhf_(accNx[0] + bgN.x + rv0x * (accNh[0] + bn.x));
        float nv0y = tanhf_(accNx[1] + bgN.y + rv0y * (accNh[1] + bn.y));
        float nv1x = tanhf_(accNx[2] + bgN.x + rv1x * (accNh[2] + bn.x));
        float nv1y = tanhf_(accNx[3] + bgN.y + rv1y * (accNh[3] + bn.y));

        float2 h0, h1;
        h0.x = nv0x + zv0x * (ho0.x - nv0x);
        h0.y = nv0y + zv0y * (ho0.y - nv0y);
        h1.x = nv1x + zv1x * (ho1.x - nv1x);
        h1.y = nv1y + zv1y * (ho1.y - nv1y);

        // ---- store h fp32 + bf16 splits for t+1 ----
        float* hOut = g_h[(t + 1) & 1];
        __nv_bfloat16* hhiOut = g_hhi[(t + 1) & 1];
        __nv_bfloat16* hloOut = g_hlo[(t + 1) & 1];
        *(float2*)(hOut + (size_t)r0g * H + jcol) = h0;
        *(float2*)(hOut + (size_t)r1g * H + jcol) = h1;

        __nv_bfloat162 p0h, p0l, p1h, p1l;
        p0h.x = __float2bfloat16(h0.x);  p0h.y = __float2bfloat16(h0.y);
        p0l.x = __float2bfloat16(h0.x - __bfloat162float(p0h.x));
        p0l.y = __float2bfloat16(h0.y - __bfloat162float(p0h.y));
        p1h.x = __float2bfloat16(h1.x);  p1h.y = __float2bfloat16(h1.y);
        p1l.x = __float2bfloat16(h1.x - __bfloat162float(p1h.x));
        p1l.y = __float2bfloat16(h1.y - __bfloat162float(p1h.y));
        *(__nv_bfloat162*)(hhiOut + (size_t)r0g * H + jcol) = p0h;
        *(__nv_bfloat162*)(hloOut + (size_t)r0g * H + jcol) = p0l;
        *(__nv_bfloat162*)(hhiOut + (size_t)r1g * H + jcol) = p1h;
        *(__nv_bfloat162*)(hloOut + (size_t)r1g * H + jcol) = p1l;
    }
}

// ---------------------------------------------------------------------------
// Final linear: out = h_final @ w_lin^T + bias_out (h_final in g_h[0]).
// 128 CTAs x 128 thr; CTA = 4 rows, thread = 1 row x 4 cols.
// ---------------------------------------------------------------------------
__global__ __launch_bounds__(128) void final_linear(const float* __restrict__ bias_out,
                                                    float* __restrict__ out) {
    __shared__ float hsv[4 * H];
    int tid = threadIdx.x;
    int row0 = blockIdx.x * 4;
    {
        const float4* src = (const float4*)(g_h[0] + (size_t)row0 * H);
        float4* dst = (float4*)hsv;
        #pragma unroll
        for (int i = 0; i < 2; i++) dst[tid + i * 128] = src[tid + i * 128];
    }
    __syncthreads();

    int c = tid & 31;   // 4 cols: 4c..4c+3
    int r = tid >> 5;   // row 0..3
    unsigned long long acc[2] = {0ULL, 0ULL};

    #pragma unroll 4
    for (int k = 0; k < H; k++) {
        ulonglong2 wv = *(const ulonglong2*)&g_WLt[k * OUT + 4 * c];
        unsigned long long hv = dup2(hsv[r * H + k]);
        fma2(acc[0], hv, wv.x);
        fma2(acc[1], hv, wv.y);
    }
    float b0 = bias_out[4 * c + 0];
    float b1 = bias_out[4 * c + 1];
    float b2 = bias_out[4 * c + 2];
    float b3 = bias_out[4 * c + 3];
    float2 lo = unpack2(acc[0]);
    float2 hi = unpack2(acc[1]);
    float4 v = make_float4(lo.x + b0, lo.y + b1, hi.x + b2, hi.y + b3);
    *(float4*)&out[(size_t)(row0 + r) * OUT + 4 * c] = v;
}

// ---------------------------------------------------------------------------
// Launch
// ---------------------------------------------------------------------------
extern "C" void kernel_launch(void* const* d_in, const int* in_sizes, int n_in,
                              void* d_out, int out_size) {
    const float* x        = (const float*)d_in[0];
    const float* w_ih     = (const float*)d_in[1];
    const float* w_hh     = (const float*)d_in[2];
    const float* bias_g   = (const float*)d_in[3];
    const float* bias_n   = (const float*)d_in[4];
    const float* w_lin    = (const float*)d_in[5];
    const float* bias_out = (const float*)d_in[6];
    float* out = (float*)d_out;
    (void)in_sizes; (void)n_in; (void)out_size;

    (void)cudaFuncSetAttribute(gru_mma,
                               cudaFuncAttributeMaxDynamicSharedMemorySize,
                               SMEM_MMA);

    split_x<<<(BT * IN / 4 + 255) / 256, 256>>>(x);
    prep_kernel<<<768, 256>>>(w_ih, w_hh, w_lin);

    gru_mma<<<NBLK, 256, SMEM_MMA>>>(nullptr, bias_g, bias_n);

    final_linear<<<B / 4, 128>>>(bias_out, out);
}